// round 12
// baseline (speedup 1.0000x reference)
#include <cuda_runtime.h>
#include <cuda_bf16.h>
#include <cstdint>
#include <math.h>

#define Bb 4
#define Ii 32
#define Nn 4096
#define Dd 64
#define WP 0.5f

#define STR 68          // padded SMEM row stride (floats)
#define CQS 8           // column splits per row band
#define CT_PER 8        // 64-col tiles per block

// ---------------- device scratch ----------------
__device__ int      g_dtype;
__device__ int      g_inst[Bb * Nn];
__device__ int      g_cnt[Bb * Ii];
__device__ float    g_lp[Bb * Ii];
__device__ float    g_ln[Bb * Ii];
__device__ unsigned g_maskb[Bb * Ii * (Nn / 32)];   // 16384 words
__device__ float    g_xtf[Bb * Nn * Dd];
__device__ float    g_te[Bb * Nn];
__device__ float    g_se[Bb * Nn];
__device__ float    g_ps[Bb * Nn];

__device__ __forceinline__ float to_tf32(float v) {
    float r;
    asm("cvt.rna.tf32.f32 %0, %1;" : "=f"(r) : "f"(v));
    return r;
}
__device__ __forceinline__ void mma8(float* d, const uint32_t* a, uint32_t b0, uint32_t b1) {
    asm volatile(
        "mma.sync.aligned.m16n8k8.row.col.f32.tf32.tf32.f32 "
        "{%0,%1,%2,%3}, {%4,%5,%6,%7}, {%8,%9}, {%0,%1,%2,%3};"
        : "+f"(d[0]), "+f"(d[1]), "+f"(d[2]), "+f"(d[3])
        : "r"(a[0]), "r"(a[1]), "r"(a[2]), "r"(a[3]), "r"(b0), "r"(b1));
}
__device__ __forceinline__ uint32_t smem_u32(const void* p) {
    return (uint32_t)__cvta_generic_to_shared(p);
}
__device__ __forceinline__ void cpasync16(uint32_t dst, const float* src) {
    asm volatile("cp.async.cg.shared.global [%0], [%1], 16;" :: "r"(dst), "l"(src));
}
#define CP_COMMIT() asm volatile("cp.async.commit_group;" ::: "memory")
#define CP_WAIT1()  asm volatile("cp.async.wait_group 1;" ::: "memory")
#define CP_WAIT0()  asm volatile("cp.async.wait_group 0;" ::: "memory")

// ---------------- kernel 1: detect label dtype + zero tiny arrays ----------------
__global__ void detect_kernel(const unsigned int* lab_words) {
    __shared__ int notInt, notFloat;
    int t = threadIdx.x;
    if (t == 0) { notInt = 0; notFloat = 0; }
    __syncthreads();
    int vi = 0, vf = 0;
    for (int i = t; i < 4096; i += blockDim.x) {
        unsigned int w = lab_words[i];
        if (w > 1u) vi = 1;
        if (w != 0u && w != 0x3F800000u) vf = 1;
    }
    if (vi) atomicOr(&notInt, 1);
    if (vf) atomicOr(&notFloat, 1);
    __syncthreads();
    if (t == 0) g_dtype = (!notInt) ? 1 : ((!notFloat) ? 2 : 0);
    if (t < Bb * Ii) { g_cnt[t] = 0; g_lp[t] = 0.f; g_ln[t] = 0.f; }
}

// ---------------- kernel 1b: flat zero of 16384-word scratch arrays ----------------
__global__ void zero_kernel() {
    int t = blockIdx.x * 256 + threadIdx.x;   // 64*256 = 16384
    g_inst[t]  = -1;
    g_maskb[t] = 0u;
    g_te[t] = 0.f;
    g_se[t] = 0.f;
    g_ps[t] = 0.f;
}

// ---------------- kernel 2: full-scan label pass (inst + cnt + bitmask) ----------------
// one thread per (b,i,n) element; warp covers 32 consecutive n of one plane.
__global__ void lab_kernel(const void* lab) {
    int idx = blockIdx.x * 256 + threadIdx.x;    // 0 .. B*I*N-1
    int dt = g_dtype;
    bool v;
    if (dt == 0)      v = (((const unsigned char*)lab)[idx] != 0);
    else if (dt == 1) v = (((const int*)lab)[idx] != 0);
    else              v = (((const float*)lab)[idx] != 0.0f);

    int b = idx >> 17;            // Ii*Nn = 131072
    int i = (idx >> 12) & 31;
    int n = idx & 4095;
    if (v) g_inst[b * Nn + n] = i;

    unsigned bal = __ballot_sync(0xffffffffu, v);
    if ((threadIdx.x & 31) == 0 && bal) {
        atomicOr(&g_maskb[(b * Ii + i) * (Nn / 32) + (n >> 5)], bal);
        atomicAdd(&g_cnt[b * Ii + i], __popc(bal));
    }
}

// ---------------- kernel 2b: tf32 round x ----------------
__global__ void cvt_kernel(const float* __restrict__ x) {
    int t = blockIdx.x * 256 + threadIdx.x;      // 262144 threads, one float4 each
    float4 v = *(const float4*)(x + (size_t)t * 4);
    v.x = to_tf32(v.x); v.y = to_tf32(v.y); v.z = to_tf32(v.z); v.w = to_tf32(v.w);
    *(float4*)(g_xtf + (size_t)t * 4) = v;
}

// ---------------- kernel 3: tf32 mma sim, occ-3, split accumulators ----------------
// 1024 blocks x 256 threads. Block: 128 rows x 512 cols.
__global__ __launch_bounds__(256, 3) void sim_kernel() {
    __shared__ float Bs[2][64 * STR];   // 34816 bytes

    int tid = threadIdx.x;
    int wid = tid >> 5;
    int lid = tid & 31;
    int g   = lid >> 2;
    int tg  = lid & 3;

    int blk = blockIdx.x;
    int b   = blk >> 8;
    int r   = blk & 255;
    int rt  = r >> 3;
    int cq  = r & 7;
    int p0  = rt * 128;
    int c0  = cq * 512;
    const float* xb = g_xtf + (size_t)b * Nn * Dd;

    int ldr = tid >> 4;      // 0..15
    int cg  = tid & 15;

    // stage A (128 rows) through the two buffers, extract register fragments
    #pragma unroll
    for (int h = 0; h < 2; h++)
        #pragma unroll
        for (int t = 0; t < 4; t++) {
            int row = ldr + t * 16;
            float4 v = *(const float4*)(xb + (size_t)(p0 + h * 64 + row) * Dd + cg * 4);
            *(float4*)(&Bs[h][row * STR + cg * 4]) = v;
        }
    __syncthreads();

    uint32_t af[8][4];
    {
        const float* Ab = Bs[wid >> 2];
        int rc = (wid & 3) * 16 + g;
        #pragma unroll
        for (int kk = 0; kk < 8; kk++) {
            af[kk][0] = __float_as_uint(Ab[rc * STR + kk * 8 + tg]);
            af[kk][1] = __float_as_uint(Ab[(rc + 8) * STR + kk * 8 + tg]);
            af[kk][2] = __float_as_uint(Ab[rc * STR + kk * 8 + tg + 4]);
            af[kk][3] = __float_as_uint(Ab[(rc + 8) * STR + kk * 8 + tg + 4]);
        }
    }
    __syncthreads();   // A reads done; buffers free for B pipeline

    int r0g = p0 + wid * 16 + g;
    int ip0 = g_inst[b * Nn + r0g];
    int ip1 = g_inst[b * Nn + r0g + 8];
    int mb0 = (ip0 >= 0) ? (b * Ii + ip0) * (Nn / 32) : -1;
    int mb1 = (ip1 >= 0) ? (b * Ii + ip1) * (Nn / 32) : -1;

    uint32_t bsm[2] = { smem_u32(&Bs[0][0]), smem_u32(&Bs[1][0]) };
    uint32_t dsto = (uint32_t)(ldr * STR + cg * 4) * 4u;

    #pragma unroll
    for (int pre = 0; pre < 2; pre++) {
        const float* src = xb + (size_t)(c0 + pre * 64) * Dd;
        #pragma unroll
        for (int t = 0; t < 4; t++)
            cpasync16(bsm[pre] + dsto + t * 16 * STR * 4, src + (size_t)(ldr + t * 16) * Dd + cg * 4);
        CP_COMMIT();
    }

    // split accumulators to break serial FADD chains
    float te0a = 0.f, te0b = 0.f, te1a = 0.f, te1b = 0.f;
    float se0 = 0.f, se1 = 0.f, ps0 = 0.f, ps1 = 0.f;

    #pragma unroll 1
    for (int ct = 0; ct < CT_PER; ct++) {
        int buf = ct & 1;
        if (ct == CT_PER - 1) CP_WAIT0(); else CP_WAIT1();
        __syncthreads();

        const float* Bp = Bs[buf];
        int wbase = cq * 16 + ct * 2;
        unsigned m0[2], m1[2];
        #pragma unroll
        for (int j = 0; j < 2; j++) {
            m0[j] = (mb0 >= 0) ? g_maskb[mb0 + wbase + j] : 0u;
            m1[j] = (mb1 >= 0) ? g_maskb[mb1 + wbase + j] : 0u;
        }

        // two groups of 4 n-tiles: acc footprint 16 regs instead of 32
        #pragma unroll
        for (int gr = 0; gr < 2; gr++) {
            float acc[4][4];
            #pragma unroll
            for (int nt = 0; nt < 4; nt++)
                #pragma unroll
                for (int j = 0; j < 4; j++) acc[nt][j] = 0.f;

            #pragma unroll
            for (int kk = 0; kk < 8; kk++) {
                #pragma unroll
                for (int nt = 0; nt < 4; nt++) {
                    int nb = (gr * 4 + nt) * 8 + g;
                    uint32_t b0 = __float_as_uint(Bp[nb * STR + kk * 8 + tg]);
                    uint32_t b1 = __float_as_uint(Bp[nb * STR + kk * 8 + tg + 4]);
                    mma8(acc[nt], af[kk], b0, b1);
                }
            }

            #pragma unroll
            for (int nt = 0; nt < 4; nt++) {
                int ntg = gr * 4 + nt;
                int cb = ntg * 8 + 2 * tg;
                int wj = cb >> 5;
                unsigned w0 = m0[wj], w1 = m1[wj];
                int bit0 = cb & 31, bit1 = (cb + 1) & 31;
                float s00 = acc[nt][0], s01 = acc[nt][1];
                float s10 = acc[nt][2], s11 = acc[nt][3];
                float e00 = __expf(s00), e01 = __expf(s01);
                float e10 = __expf(s10), e11 = __expf(s11);
                if (nt & 1) { te0b += e00 + e01; te1b += e10 + e11; }
                else        { te0a += e00 + e01; te1a += e10 + e11; }
                if ((w0 >> bit0) & 1u) { se0 += e00; float d = s00 - 1.f; ps0 = fmaf(d, d, ps0); }
                if ((w0 >> bit1) & 1u) { se0 += e01; float d = s01 - 1.f; ps0 = fmaf(d, d, ps0); }
                if ((w1 >> bit0) & 1u) { se1 += e10; float d = s10 - 1.f; ps1 = fmaf(d, d, ps1); }
                if ((w1 >> bit1) & 1u) { se1 += e11; float d = s11 - 1.f; ps1 = fmaf(d, d, ps1); }
            }
        }

        __syncthreads();   // all reads of Bs[buf] done
        if (ct + 2 < CT_PER) {
            const float* src = xb + (size_t)(c0 + (ct + 2) * 64) * Dd;
            #pragma unroll
            for (int t = 0; t < 4; t++)
                cpasync16(bsm[buf] + dsto + t * 16 * STR * 4, src + (size_t)(ldr + t * 16) * Dd + cg * 4);
            CP_COMMIT();
        }
    }

    float te0 = te0a + te0b;
    float te1 = te1a + te1b;
    #pragma unroll
    for (int off = 2; off > 0; off >>= 1) {
        te0 += __shfl_down_sync(0xffffffffu, te0, off, 4);
        te1 += __shfl_down_sync(0xffffffffu, te1, off, 4);
        se0 += __shfl_down_sync(0xffffffffu, se0, off, 4);
        se1 += __shfl_down_sync(0xffffffffu, se1, off, 4);
        ps0 += __shfl_down_sync(0xffffffffu, ps0, off, 4);
        ps1 += __shfl_down_sync(0xffffffffu, ps1, off, 4);
    }
    if (tg == 0) {
        size_t o0 = (size_t)b * Nn + r0g;
        atomicAdd(&g_te[o0], te0);
        atomicAdd(&g_se[o0], se0);
        atomicAdd(&g_ps[o0], ps0);
        atomicAdd(&g_te[o0 + 8], te1);
        atomicAdd(&g_se[o0 + 8], se1);
        atomicAdd(&g_ps[o0 + 8], ps1);
    }
}

// ---------------- kernel 4: per-row log + per-instance fold ----------------
__global__ void row_kernel() {
    __shared__ float s_lp[Ii];
    __shared__ float s_ln[Ii];
    int t = threadIdx.x;
    int idx = blockIdx.x * 256 + t;
    int b = idx >> 12;
    if (t < Ii) { s_lp[t] = 0.f; s_ln[t] = 0.f; }
    __syncthreads();
    int i = g_inst[idx];
    if (i >= 0) {
        atomicAdd(&s_lp[i], g_ps[idx]);
        float neg = g_te[idx] - g_se[idx];
        atomicAdd(&s_ln[i], logf(fmaxf(neg, 1e-30f)));
    }
    __syncthreads();
    if (t < Ii) {
        if (s_lp[t] != 0.f) atomicAdd(&g_lp[b * Ii + t], s_lp[t]);
        if (s_ln[t] != 0.f) atomicAdd(&g_ln[b * Ii + t], s_ln[t]);
    }
}

// ---------------- kernel 5: tiny finish ----------------
__global__ void final_kernel(float* out) {
    __shared__ float s_red[128];
    int t = threadIdx.x;
    float cnt = (float)g_cnt[t];
    float valid = (cnt >= 5.0f) ? 1.0f : 0.0f;
    float lp = g_lp[t] / fmaxf(cnt * cnt, 1.0f);
    float ln = g_ln[t] / fmaxf(cnt, 1.0f);
    s_red[t] = valid * (WP * lp + (1.0f - WP) * ln);
    __syncthreads();
    for (int off = 64; off > 0; off >>= 1) {
        if (t < off) s_red[t] += s_red[t + off];
        __syncthreads();
    }
    if (t == 0) out[0] = s_red[0] / (float)(Bb * Ii);
}

// ---------------- launch ----------------
extern "C" void kernel_launch(void* const* d_in, const int* in_sizes, int n_in,
                              void* d_out, int out_size) {
    const float* x   = (const float*)d_in[0];
    const void*  lab = d_in[1];
    float* out = (float*)d_out;

    detect_kernel<<<1, 256>>>((const unsigned int*)lab);
    zero_kernel<<<64, 256>>>();
    lab_kernel<<<(Bb * Ii * Nn) / 256, 256>>>(lab);
    cvt_kernel<<<(Bb * Nn * Dd / 4) / 256, 256>>>(x);
    sim_kernel<<<Bb * 32 * CQS, 256>>>();
    row_kernel<<<Bb * Nn / 256, 256>>>();
    final_kernel<<<1, 128>>>(out);
}

// round 16
// speedup vs baseline: 1.9237x; 1.9237x over previous
#include <cuda_runtime.h>
#include <cuda_bf16.h>
#include <cstdint>
#include <math.h>

#define Bb 4
#define Ii 32
#define Nn 4096
#define Dd 64
#define WP 0.5f

#define USTR 36         // B/A SMEM row stride in uints (bf16x2); banks 4g+tg -> conflict-free
#define CQS 8
#define CT_PER 8

// ---------------- device scratch ----------------
__device__ int      g_dtype;
__device__ int      g_inst[Bb * Nn];
__device__ int      g_cnt[Bb * Ii];
__device__ float    g_lp[Bb * Ii];
__device__ float    g_ln[Bb * Ii];
__device__ unsigned g_maskb[Bb * Ii * (Nn / 32)];
__device__ unsigned g_xbf[Bb * Nn * (Dd / 2)];   // bf16x2-packed features (2 MB)
__device__ float    g_te[Bb * Nn];
__device__ float    g_se[Bb * Nn];
__device__ float    g_ps[Bb * Nn];

__device__ __forceinline__ unsigned pack_bf16x2(float lo, float hi) {
    unsigned r;
    asm("cvt.rn.bf16x2.f32 %0, %1, %2;" : "=r"(r) : "f"(hi), "f"(lo));
    return r;
}
__device__ __forceinline__ void mma16(float* d, const uint32_t* a, uint32_t b0, uint32_t b1) {
    asm volatile(
        "mma.sync.aligned.m16n8k16.row.col.f32.bf16.bf16.f32 "
        "{%0,%1,%2,%3}, {%4,%5,%6,%7}, {%8,%9}, {%0,%1,%2,%3};"
        : "+f"(d[0]), "+f"(d[1]), "+f"(d[2]), "+f"(d[3])
        : "r"(a[0]), "r"(a[1]), "r"(a[2]), "r"(a[3]), "r"(b0), "r"(b1));
}
__device__ __forceinline__ uint32_t smem_u32(const void* p) {
    return (uint32_t)__cvta_generic_to_shared(p);
}
__device__ __forceinline__ void cpasync16(uint32_t dst, const void* src) {
    asm volatile("cp.async.cg.shared.global [%0], [%1], 16;" :: "r"(dst), "l"(src));
}
#define CP_COMMIT() asm volatile("cp.async.commit_group;" ::: "memory")
#define CP_WAIT1()  asm volatile("cp.async.wait_group 1;" ::: "memory")
#define CP_WAIT0()  asm volatile("cp.async.wait_group 0;" ::: "memory")

// ---------------- kernel 1: detect label dtype + zero tiny arrays ----------------
__global__ void detect_kernel(const unsigned int* lab_words) {
    __shared__ int notInt, notFloat;
    int t = threadIdx.x;
    if (t == 0) { notInt = 0; notFloat = 0; }
    __syncthreads();
    int vi = 0, vf = 0;
    for (int i = t; i < 4096; i += blockDim.x) {
        unsigned int w = lab_words[i];
        if (w > 1u) vi = 1;
        if (w != 0u && w != 0x3F800000u) vf = 1;
    }
    if (vi) atomicOr(&notInt, 1);
    if (vf) atomicOr(&notFloat, 1);
    __syncthreads();
    if (t == 0) g_dtype = (!notInt) ? 1 : ((!notFloat) ? 2 : 0);
    if (t < Bb * Ii) { g_cnt[t] = 0; g_lp[t] = 0.f; g_ln[t] = 0.f; }
}

// ---------------- kernel 1b: flat zero of 16384-word scratch ----------------
__global__ void zero_kernel() {
    int t = blockIdx.x * 256 + threadIdx.x;
    g_inst[t]  = -1;
    g_maskb[t] = 0u;
    g_te[t] = 0.f;
    g_se[t] = 0.f;
    g_ps[t] = 0.f;
}

// ---------------- kernel 2: full-scan label pass ----------------
__global__ void lab_kernel(const void* lab) {
    int idx = blockIdx.x * 256 + threadIdx.x;
    int dt = g_dtype;
    bool v;
    if (dt == 0)      v = (((const unsigned char*)lab)[idx] != 0);
    else if (dt == 1) v = (((const int*)lab)[idx] != 0);
    else              v = (((const float*)lab)[idx] != 0.0f);

    int b = idx >> 17;
    int i = (idx >> 12) & 31;
    int n = idx & 4095;
    if (v) g_inst[b * Nn + n] = i;

    unsigned bal = __ballot_sync(0xffffffffu, v);
    if ((threadIdx.x & 31) == 0 && bal) {
        atomicOr(&g_maskb[(b * Ii + i) * (Nn / 32) + (n >> 5)], bal);
        atomicAdd(&g_cnt[b * Ii + i], __popc(bal));
    }
}

// ---------------- kernel 2b: f32 -> packed bf16x2 ----------------
__global__ void cvt_kernel(const float* __restrict__ x) {
    int t = blockIdx.x * 256 + threadIdx.x;   // 131072 threads, one uint4 (8 floats) each
    float4 v1 = *(const float4*)(x + (size_t)t * 8);
    float4 v2 = *(const float4*)(x + (size_t)t * 8 + 4);
    uint4 o;
    o.x = pack_bf16x2(v1.x, v1.y);
    o.y = pack_bf16x2(v1.z, v1.w);
    o.z = pack_bf16x2(v2.x, v2.y);
    o.w = pack_bf16x2(v2.z, v2.w);
    *(uint4*)(g_xbf + (size_t)t * 4) = o;
}

// ---------------- kernel 3: bf16 mma sim (R9 structure) ----------------
// 1024 blocks x 256 threads. Block: 128 rows x 512 cols.
__global__ __launch_bounds__(256, 2) void sim_kernel() {
    __shared__ unsigned Bs[2][64 * USTR];   // 2 x 9216 bytes

    int tid = threadIdx.x;
    int wid = tid >> 5;
    int lid = tid & 31;
    int g   = lid >> 2;
    int tg  = lid & 3;

    int blk = blockIdx.x;
    int b   = blk >> 8;
    int r   = blk & 255;
    int rt  = r >> 3;
    int cq  = r & 7;
    int p0  = rt * 128;
    int c0  = cq * 512;
    const unsigned* xb = g_xbf + (size_t)b * Nn * (Dd / 2);

    // stage A (128 rows x 32 uints) through the two buffers
    #pragma unroll
    for (int t = 0; t < 4; t++) {
        int c = tid + 256 * t;          // chunk 0..1023
        int row = c >> 3;               // 0..127
        int seg = c & 7;                // uint4 seg 0..7
        uint4 v = *(const uint4*)(xb + (size_t)(p0 + row) * 32 + seg * 4);
        *(uint4*)(&Bs[row >> 6][(row & 63) * USTR + seg * 4]) = v;
    }
    __syncthreads();

    // A fragments: 4 k16-steps x 4 regs (bf16x2-packed)
    uint32_t af[4][4];
    {
        const unsigned* Ab = Bs[wid >> 2];
        int rc = (wid & 3) * 16 + g;
        #pragma unroll
        for (int kk = 0; kk < 4; kk++) {
            af[kk][0] = Ab[rc * USTR + kk * 8 + tg];
            af[kk][1] = Ab[(rc + 8) * USTR + kk * 8 + tg];
            af[kk][2] = Ab[rc * USTR + kk * 8 + tg + 4];
            af[kk][3] = Ab[(rc + 8) * USTR + kk * 8 + tg + 4];
        }
    }
    __syncthreads();   // A reads done; buffers free for B pipeline

    int r0g = p0 + wid * 16 + g;
    int ip0 = g_inst[b * Nn + r0g];
    int ip1 = g_inst[b * Nn + r0g + 8];
    int mb0 = (ip0 >= 0) ? (b * Ii + ip0) * (Nn / 32) : -1;
    int mb1 = (ip1 >= 0) ? (b * Ii + ip1) * (Nn / 32) : -1;

    uint32_t bsm[2] = { smem_u32(&Bs[0][0]), smem_u32(&Bs[1][0]) };
    // B staging: thread -> row = tid>>2 (0..63), two 16B segs
    int brow = tid >> 2;
    int bseg = (tid & 3) * 2;
    uint32_t dst0 = (uint32_t)(brow * USTR + bseg * 4) * 4u;
    uint32_t dst1 = dst0 + 16u;

    #pragma unroll
    for (int pre = 0; pre < 2; pre++) {
        const unsigned* src = xb + (size_t)(c0 + pre * 64 + brow) * 32;
        cpasync16(bsm[pre] + dst0, src + bseg * 4);
        cpasync16(bsm[pre] + dst1, src + bseg * 4 + 4);
        CP_COMMIT();
    }

    float te0a = 0.f, te0b = 0.f, te1a = 0.f, te1b = 0.f;
    float se0 = 0.f, se1 = 0.f, ps0 = 0.f, ps1 = 0.f;

    #pragma unroll 1
    for (int ct = 0; ct < CT_PER; ct++) {
        int buf = ct & 1;
        if (ct == CT_PER - 1) CP_WAIT0(); else CP_WAIT1();
        __syncthreads();

        float acc[8][4];
        #pragma unroll
        for (int nt = 0; nt < 8; nt++)
            #pragma unroll
            for (int j = 0; j < 4; j++) acc[nt][j] = 0.f;

        const unsigned* Bp = Bs[buf];
        #pragma unroll
        for (int kk = 0; kk < 4; kk++) {
            #pragma unroll
            for (int nt = 0; nt < 8; nt++) {
                int nb = nt * 8 + g;
                uint32_t b0 = Bp[nb * USTR + kk * 8 + tg];
                uint32_t b1 = Bp[nb * USTR + kk * 8 + tg + 4];
                mma16(acc[nt], af[kk], b0, b1);
            }
        }

        int wbase = cq * 16 + ct * 2;
        unsigned m0[2], m1[2];
        #pragma unroll
        for (int j = 0; j < 2; j++) {
            m0[j] = (mb0 >= 0) ? g_maskb[mb0 + wbase + j] : 0u;
            m1[j] = (mb1 >= 0) ? g_maskb[mb1 + wbase + j] : 0u;
        }

        #pragma unroll
        for (int nt = 0; nt < 8; nt++) {
            int cb = nt * 8 + 2 * tg;
            int wj = cb >> 5;
            unsigned w0 = m0[wj], w1 = m1[wj];
            int bit0 = cb & 31, bit1 = (cb + 1) & 31;
            float s00 = acc[nt][0], s01 = acc[nt][1];
            float s10 = acc[nt][2], s11 = acc[nt][3];
            float e00 = __expf(s00), e01 = __expf(s01);
            float e10 = __expf(s10), e11 = __expf(s11);
            if (nt & 1) { te0b += e00 + e01; te1b += e10 + e11; }
            else        { te0a += e00 + e01; te1a += e10 + e11; }
            if ((w0 >> bit0) & 1u) { se0 += e00; float d = s00 - 1.f; ps0 = fmaf(d, d, ps0); }
            if ((w0 >> bit1) & 1u) { se0 += e01; float d = s01 - 1.f; ps0 = fmaf(d, d, ps0); }
            if ((w1 >> bit0) & 1u) { se1 += e10; float d = s10 - 1.f; ps1 = fmaf(d, d, ps1); }
            if ((w1 >> bit1) & 1u) { se1 += e11; float d = s11 - 1.f; ps1 = fmaf(d, d, ps1); }
        }

        __syncthreads();
        if (ct + 2 < CT_PER) {
            const unsigned* src = xb + (size_t)(c0 + (ct + 2) * 64 + brow) * 32;
            cpasync16(bsm[buf] + dst0, src + bseg * 4);
            cpasync16(bsm[buf] + dst1, src + bseg * 4 + 4);
            CP_COMMIT();
        }
    }

    float te0 = te0a + te0b;
    float te1 = te1a + te1b;
    #pragma unroll
    for (int off = 2; off > 0; off >>= 1) {
        te0 += __shfl_down_sync(0xffffffffu, te0, off, 4);
        te1 += __shfl_down_sync(0xffffffffu, te1, off, 4);
        se0 += __shfl_down_sync(0xffffffffu, se0, off, 4);
        se1 += __shfl_down_sync(0xffffffffu, se1, off, 4);
        ps0 += __shfl_down_sync(0xffffffffu, ps0, off, 4);
        ps1 += __shfl_down_sync(0xffffffffu, ps1, off, 4);
    }
    if (tg == 0) {
        size_t o0 = (size_t)b * Nn + r0g;
        atomicAdd(&g_te[o0], te0);
        atomicAdd(&g_se[o0], se0);
        atomicAdd(&g_ps[o0], ps0);
        atomicAdd(&g_te[o0 + 8], te1);
        atomicAdd(&g_se[o0 + 8], se1);
        atomicAdd(&g_ps[o0 + 8], ps1);
    }
}

// ---------------- kernel 4: per-row log + per-instance fold ----------------
__global__ void row_kernel() {
    __shared__ float s_lp[Ii];
    __shared__ float s_ln[Ii];
    int t = threadIdx.x;
    int idx = blockIdx.x * 256 + t;
    int b = idx >> 12;
    if (t < Ii) { s_lp[t] = 0.f; s_ln[t] = 0.f; }
    __syncthreads();
    int i = g_inst[idx];
    if (i >= 0) {
        atomicAdd(&s_lp[i], g_ps[idx]);
        float neg = g_te[idx] - g_se[idx];
        atomicAdd(&s_ln[i], logf(fmaxf(neg, 1e-30f)));
    }
    __syncthreads();
    if (t < Ii) {
        if (s_lp[t] != 0.f) atomicAdd(&g_lp[b * Ii + t], s_lp[t]);
        if (s_ln[t] != 0.f) atomicAdd(&g_ln[b * Ii + t], s_ln[t]);
    }
}

// ---------------- kernel 5: tiny finish ----------------
__global__ void final_kernel(float* out) {
    __shared__ float s_red[128];
    int t = threadIdx.x;
    float cnt = (float)g_cnt[t];
    float valid = (cnt >= 5.0f) ? 1.0f : 0.0f;
    float lp = g_lp[t] / fmaxf(cnt * cnt, 1.0f);
    float ln = g_ln[t] / fmaxf(cnt, 1.0f);
    s_red[t] = valid * (WP * lp + (1.0f - WP) * ln);
    __syncthreads();
    for (int off = 64; off > 0; off >>= 1) {
        if (t < off) s_red[t] += s_red[t + off];
        __syncthreads();
    }
    if (t == 0) out[0] = s_red[0] / (float)(Bb * Ii);
}

// ---------------- launch ----------------
extern "C" void kernel_launch(void* const* d_in, const int* in_sizes, int n_in,
                              void* d_out, int out_size) {
    const float* x   = (const float*)d_in[0];
    const void*  lab = d_in[1];
    float* out = (float*)d_out;

    detect_kernel<<<1, 256>>>((const unsigned int*)lab);
    zero_kernel<<<64, 256>>>();
    lab_kernel<<<(Bb * Ii * Nn) / 256, 256>>>(lab);
    cvt_kernel<<<(Bb * Nn * Dd / 8) / 256, 256>>>(x);
    sim_kernel<<<Bb * 32 * CQS, 256>>>();
    row_kernel<<<Bb * Nn / 256, 256>>>();
    final_kernel<<<1, 128>>>(out);
}

// round 17
// speedup vs baseline: 1.9425x; 1.0098x over previous
#include <cuda_runtime.h>
#include <cuda_bf16.h>
#include <cstdint>
#include <math.h>

#define Bb 4
#define Ii 32
#define Nn 4096
#define Dd 64
#define WP 0.5f

#define USTR 36         // B/A SMEM row stride in uints (bf16x2); banks 4g+tg -> conflict-free
#define CQS 8
#define CT_PER 8

// ---------------- device scratch ----------------
__device__ int      g_dtype;
__device__ int      g_inst[Bb * Nn];
__device__ int      g_cnt[Bb * Ii];
__device__ float    g_lp[Bb * Ii];
__device__ float    g_ln[Bb * Ii];
__device__ unsigned g_maskb[Bb * Ii * (Nn / 32)];
__device__ unsigned g_xbf[Bb * Nn * (Dd / 2)];   // bf16x2-packed features (2 MB)
__device__ float    g_te[Bb * Nn];
__device__ float    g_se[Bb * Nn];
__device__ float    g_ps[Bb * Nn];

__device__ __forceinline__ unsigned pack_bf16x2(float lo, float hi) {
    unsigned r;
    asm("cvt.rn.bf16x2.f32 %0, %1, %2;" : "=r"(r) : "f"(hi), "f"(lo));
    return r;
}
__device__ __forceinline__ void mma16(float* d, const uint32_t* a, uint32_t b0, uint32_t b1) {
    asm volatile(
        "mma.sync.aligned.m16n8k16.row.col.f32.bf16.bf16.f32 "
        "{%0,%1,%2,%3}, {%4,%5,%6,%7}, {%8,%9}, {%0,%1,%2,%3};"
        : "+f"(d[0]), "+f"(d[1]), "+f"(d[2]), "+f"(d[3])
        : "r"(a[0]), "r"(a[1]), "r"(a[2]), "r"(a[3]), "r"(b0), "r"(b1));
}
__device__ __forceinline__ uint32_t smem_u32(const void* p) {
    return (uint32_t)__cvta_generic_to_shared(p);
}
__device__ __forceinline__ void cpasync16(uint32_t dst, const void* src) {
    asm volatile("cp.async.cg.shared.global [%0], [%1], 16;" :: "r"(dst), "l"(src));
}
#define CP_COMMIT() asm volatile("cp.async.commit_group;" ::: "memory")
#define CP_WAIT1()  asm volatile("cp.async.wait_group 1;" ::: "memory")
#define CP_WAIT0()  asm volatile("cp.async.wait_group 0;" ::: "memory")

// ---------------- kernel 1: detect label dtype + zero tiny arrays ----------------
__global__ void detect_kernel(const unsigned int* lab_words) {
    __shared__ int notInt, notFloat;
    int t = threadIdx.x;
    if (t == 0) { notInt = 0; notFloat = 0; }
    __syncthreads();
    int vi = 0, vf = 0;
    for (int i = t; i < 4096; i += blockDim.x) {
        unsigned int w = lab_words[i];
        if (w > 1u) vi = 1;
        if (w != 0u && w != 0x3F800000u) vf = 1;
    }
    if (vi) atomicOr(&notInt, 1);
    if (vf) atomicOr(&notFloat, 1);
    __syncthreads();
    if (t == 0) g_dtype = (!notInt) ? 1 : ((!notFloat) ? 2 : 0);
    if (t < Bb * Ii) { g_cnt[t] = 0; g_lp[t] = 0.f; g_ln[t] = 0.f; }
}

// ---------------- kernel 1b: flat zero of 16384-word scratch ----------------
__global__ void zero_kernel() {
    int t = blockIdx.x * 256 + threadIdx.x;
    g_inst[t]  = -1;
    g_maskb[t] = 0u;
    g_te[t] = 0.f;
    g_se[t] = 0.f;
    g_ps[t] = 0.f;
}

// ---------------- kernel 2: full-scan label pass ----------------
__global__ void lab_kernel(const void* lab) {
    int idx = blockIdx.x * 256 + threadIdx.x;
    int dt = g_dtype;
    bool v;
    if (dt == 0)      v = (((const unsigned char*)lab)[idx] != 0);
    else if (dt == 1) v = (((const int*)lab)[idx] != 0);
    else              v = (((const float*)lab)[idx] != 0.0f);

    int b = idx >> 17;
    int i = (idx >> 12) & 31;
    int n = idx & 4095;
    if (v) g_inst[b * Nn + n] = i;

    unsigned bal = __ballot_sync(0xffffffffu, v);
    if ((threadIdx.x & 31) == 0 && bal) {
        atomicOr(&g_maskb[(b * Ii + i) * (Nn / 32) + (n >> 5)], bal);
        atomicAdd(&g_cnt[b * Ii + i], __popc(bal));
    }
}

// ---------------- kernel 2b: f32 -> packed bf16x2 ----------------
__global__ void cvt_kernel(const float* __restrict__ x) {
    int t = blockIdx.x * 256 + threadIdx.x;   // 131072 threads, one uint4 (8 floats) each
    float4 v1 = *(const float4*)(x + (size_t)t * 8);
    float4 v2 = *(const float4*)(x + (size_t)t * 8 + 4);
    uint4 o;
    o.x = pack_bf16x2(v1.x, v1.y);
    o.y = pack_bf16x2(v1.z, v1.w);
    o.z = pack_bf16x2(v2.x, v2.y);
    o.w = pack_bf16x2(v2.z, v2.w);
    *(uint4*)(g_xbf + (size_t)t * 4) = o;
}

// ---------------- kernel 3: bf16 mma sim (R9 structure, occ 3) ----------------
// 1024 blocks x 256 threads. Block: 128 rows x 512 cols.
__global__ __launch_bounds__(256, 3) void sim_kernel() {
    __shared__ unsigned Bs[2][64 * USTR];   // 2 x 9216 bytes

    int tid = threadIdx.x;
    int wid = tid >> 5;
    int lid = tid & 31;
    int g   = lid >> 2;
    int tg  = lid & 3;

    int blk = blockIdx.x;
    int b   = blk >> 8;
    int r   = blk & 255;
    int rt  = r >> 3;
    int cq  = r & 7;
    int p0  = rt * 128;
    int c0  = cq * 512;
    const unsigned* xb = g_xbf + (size_t)b * Nn * (Dd / 2);

    // stage A (128 rows x 32 uints) through the two buffers
    #pragma unroll
    for (int t = 0; t < 4; t++) {
        int c = tid + 256 * t;          // chunk 0..1023
        int row = c >> 3;               // 0..127
        int seg = c & 7;                // uint4 seg 0..7
        uint4 v = *(const uint4*)(xb + (size_t)(p0 + row) * 32 + seg * 4);
        *(uint4*)(&Bs[row >> 6][(row & 63) * USTR + seg * 4]) = v;
    }
    __syncthreads();

    // A fragments: 4 k16-steps x 4 regs (bf16x2-packed)
    uint32_t af[4][4];
    {
        const unsigned* Ab = Bs[wid >> 2];
        int rc = (wid & 3) * 16 + g;
        #pragma unroll
        for (int kk = 0; kk < 4; kk++) {
            af[kk][0] = Ab[rc * USTR + kk * 8 + tg];
            af[kk][1] = Ab[(rc + 8) * USTR + kk * 8 + tg];
            af[kk][2] = Ab[rc * USTR + kk * 8 + tg + 4];
            af[kk][3] = Ab[(rc + 8) * USTR + kk * 8 + tg + 4];
        }
    }
    __syncthreads();   // A reads done; buffers free for B pipeline

    int r0g = p0 + wid * 16 + g;
    int ip0 = g_inst[b * Nn + r0g];
    int ip1 = g_inst[b * Nn + r0g + 8];
    int mb0 = (ip0 >= 0) ? (b * Ii + ip0) * (Nn / 32) : -1;
    int mb1 = (ip1 >= 0) ? (b * Ii + ip1) * (Nn / 32) : -1;

    uint32_t bsm[2] = { smem_u32(&Bs[0][0]), smem_u32(&Bs[1][0]) };
    // B staging: thread -> row = tid>>2 (0..63), two 16B segs
    int brow = tid >> 2;
    int bseg = (tid & 3) * 2;
    uint32_t dst0 = (uint32_t)(brow * USTR + bseg * 4) * 4u;
    uint32_t dst1 = dst0 + 16u;

    #pragma unroll
    for (int pre = 0; pre < 2; pre++) {
        const unsigned* src = xb + (size_t)(c0 + pre * 64 + brow) * 32;
        cpasync16(bsm[pre] + dst0, src + bseg * 4);
        cpasync16(bsm[pre] + dst1, src + bseg * 4 + 4);
        CP_COMMIT();
    }

    float te0a = 0.f, te0b = 0.f, te1a = 0.f, te1b = 0.f;
    float se0 = 0.f, se1 = 0.f, ps0 = 0.f, ps1 = 0.f;

    #pragma unroll 1
    for (int ct = 0; ct < CT_PER; ct++) {
        int buf = ct & 1;
        if (ct == CT_PER - 1) CP_WAIT0(); else CP_WAIT1();
        __syncthreads();

        float acc[8][4];
        #pragma unroll
        for (int nt = 0; nt < 8; nt++)
            #pragma unroll
            for (int j = 0; j < 4; j++) acc[nt][j] = 0.f;

        const unsigned* Bp = Bs[buf];
        #pragma unroll
        for (int kk = 0; kk < 4; kk++) {
            #pragma unroll
            for (int nt = 0; nt < 8; nt++) {
                int nb = nt * 8 + g;
                uint32_t b0 = Bp[nb * USTR + kk * 8 + tg];
                uint32_t b1 = Bp[nb * USTR + kk * 8 + tg + 4];
                mma16(acc[nt], af[kk], b0, b1);
            }
        }

        int wbase = cq * 16 + ct * 2;
        unsigned m0[2], m1[2];
        #pragma unroll
        for (int j = 0; j < 2; j++) {
            m0[j] = (mb0 >= 0) ? g_maskb[mb0 + wbase + j] : 0u;
            m1[j] = (mb1 >= 0) ? g_maskb[mb1 + wbase + j] : 0u;
        }

        #pragma unroll
        for (int nt = 0; nt < 8; nt++) {
            int cb = nt * 8 + 2 * tg;
            int wj = cb >> 5;
            unsigned w0 = m0[wj], w1 = m1[wj];
            int bit0 = cb & 31, bit1 = (cb + 1) & 31;
            float s00 = acc[nt][0], s01 = acc[nt][1];
            float s10 = acc[nt][2], s11 = acc[nt][3];
            float e00 = __expf(s00), e01 = __expf(s01);
            float e10 = __expf(s10), e11 = __expf(s11);
            if (nt & 1) { te0b += e00 + e01; te1b += e10 + e11; }
            else        { te0a += e00 + e01; te1a += e10 + e11; }
            if ((w0 >> bit0) & 1u) { se0 += e00; float d = s00 - 1.f; ps0 = fmaf(d, d, ps0); }
            if ((w0 >> bit1) & 1u) { se0 += e01; float d = s01 - 1.f; ps0 = fmaf(d, d, ps0); }
            if ((w1 >> bit0) & 1u) { se1 += e10; float d = s10 - 1.f; ps1 = fmaf(d, d, ps1); }
            if ((w1 >> bit1) & 1u) { se1 += e11; float d = s11 - 1.f; ps1 = fmaf(d, d, ps1); }
        }

        __syncthreads();
        if (ct + 2 < CT_PER) {
            const unsigned* src = xb + (size_t)(c0 + (ct + 2) * 64 + brow) * 32;
            cpasync16(bsm[buf] + dst0, src + bseg * 4);
            cpasync16(bsm[buf] + dst1, src + bseg * 4 + 4);
            CP_COMMIT();
        }
    }

    float te0 = te0a + te0b;
    float te1 = te1a + te1b;
    #pragma unroll
    for (int off = 2; off > 0; off >>= 1) {
        te0 += __shfl_down_sync(0xffffffffu, te0, off, 4);
        te1 += __shfl_down_sync(0xffffffffu, te1, off, 4);
        se0 += __shfl_down_sync(0xffffffffu, se0, off, 4);
        se1 += __shfl_down_sync(0xffffffffu, se1, off, 4);
        ps0 += __shfl_down_sync(0xffffffffu, ps0, off, 4);
        ps1 += __shfl_down_sync(0xffffffffu, ps1, off, 4);
    }
    if (tg == 0) {
        size_t o0 = (size_t)b * Nn + r0g;
        atomicAdd(&g_te[o0], te0);
        atomicAdd(&g_se[o0], se0);
        atomicAdd(&g_ps[o0], ps0);
        atomicAdd(&g_te[o0 + 8], te1);
        atomicAdd(&g_se[o0 + 8], se1);
        atomicAdd(&g_ps[o0 + 8], ps1);
    }
}

// ---------------- kernel 4: per-row log + per-instance fold ----------------
__global__ void row_kernel() {
    __shared__ float s_lp[Ii];
    __shared__ float s_ln[Ii];
    int t = threadIdx.x;
    int idx = blockIdx.x * 256 + t;
    int b = idx >> 12;
    if (t < Ii) { s_lp[t] = 0.f; s_ln[t] = 0.f; }
    __syncthreads();
    int i = g_inst[idx];
    if (i >= 0) {
        atomicAdd(&s_lp[i], g_ps[idx]);
        float neg = g_te[idx] - g_se[idx];
        atomicAdd(&s_ln[i], logf(fmaxf(neg, 1e-30f)));
    }
    __syncthreads();
    if (t < Ii) {
        if (s_lp[t] != 0.f) atomicAdd(&g_lp[b * Ii + t], s_lp[t]);
        if (s_ln[t] != 0.f) atomicAdd(&g_ln[b * Ii + t], s_ln[t]);
    }
}

// ---------------- kernel 5: tiny finish ----------------
__global__ void final_kernel(float* out) {
    __shared__ float s_red[128];
    int t = threadIdx.x;
    float cnt = (float)g_cnt[t];
    float valid = (cnt >= 5.0f) ? 1.0f : 0.0f;
    float lp = g_lp[t] / fmaxf(cnt * cnt, 1.0f);
    float ln = g_ln[t] / fmaxf(cnt, 1.0f);
    s_red[t] = valid * (WP * lp + (1.0f - WP) * ln);
    __syncthreads();
    for (int off = 64; off > 0; off >>= 1) {
        if (t < off) s_red[t] += s_red[t + off];
        __syncthreads();
    }
    if (t == 0) out[0] = s_red[0] / (float)(Bb * Ii);
}

// ---------------- launch ----------------
extern "C" void kernel_launch(void* const* d_in, const int* in_sizes, int n_in,
                              void* d_out, int out_size) {
    const float* x   = (const float*)d_in[0];
    const void*  lab = d_in[1];
    float* out = (float*)d_out;

    detect_kernel<<<1, 256>>>((const unsigned int*)lab);
    zero_kernel<<<64, 256>>>();
    lab_kernel<<<(Bb * Ii * Nn) / 256, 256>>>(lab);
    cvt_kernel<<<(Bb * Nn * Dd / 8) / 256, 256>>>(x);
    sim_kernel<<<Bb * 32 * CQS, 256>>>();
    row_kernel<<<Bb * Nn / 256, 256>>>();
    final_kernel<<<1, 128>>>(out);
}